// round 3
// baseline (speedup 1.0000x reference)
#include <cuda_runtime.h>
#include <math.h>

#define U_TOK 2048
#define D_MODEL 2048
#define NH 16
#define DH 128
#define DFF 8192
#define EPSF 1e-6f

// ---------------- scratch (static device globals; no allocations) ----------------
__device__ float g_h   [U_TOK * D_MODEL];
__device__ float g_q   [U_TOK * D_MODEL];
__device__ float g_k   [U_TOK * D_MODEL];
__device__ float g_v   [U_TOK * D_MODEL];
__device__ float g_sc  [(size_t)NH * U_TOK * U_TOK];   // 256 MB attention scores
__device__ float g_ao  [U_TOK * D_MODEL];
__device__ float g_x1  [U_TOK * D_MODEL];
__device__ float g_h2  [U_TOK * D_MODEL];
__device__ float g_ff  [U_TOK * DFF];

// ---------------- reductions ----------------
__device__ __forceinline__ float warpSum(float v) {
    #pragma unroll
    for (int o = 16; o > 0; o >>= 1) v += __shfl_xor_sync(0xffffffffu, v, o);
    return v;
}
__device__ __forceinline__ float warpMax(float v) {
    #pragma unroll
    for (int o = 16; o > 0; o >>= 1) v = fmaxf(v, __shfl_xor_sync(0xffffffffu, v, o));
    return v;
}

// ---------------- rmsnorm: one block per row ----------------
__global__ __launch_bounds__(256) void rmsnorm_kernel(
    const float* __restrict__ x, const float* __restrict__ w, float* __restrict__ out)
{
    const int row = blockIdx.x;
    const float* xr = x + (size_t)row * D_MODEL;
    float* orow = out + (size_t)row * D_MODEL;
    const int tid = threadIdx.x;

    float ss = 0.f;
    #pragma unroll
    for (int i = tid; i < D_MODEL; i += 256) { float v = xr[i]; ss = fmaf(v, v, ss); }

    __shared__ float red[8];
    float s = warpSum(ss);
    if ((tid & 31) == 0) red[tid >> 5] = s;
    __syncthreads();
    if (tid < 32) {
        float t = (tid < 8) ? red[tid] : 0.f;
        t = warpSum(t);
        if (tid == 0) red[0] = rsqrtf(t * (1.f / D_MODEL) + EPSF);
    }
    __syncthreads();
    const float inv = red[0];
    #pragma unroll
    for (int i = tid; i < D_MODEL; i += 256) orow[i] = xr[i] * inv * w[i];
}

// ---------------- softmax over rows of g_sc ----------------
__global__ __launch_bounds__(256) void softmax_kernel(float* __restrict__ S)
{
    float* p = S + (size_t)blockIdx.x * U_TOK;
    const int tid = threadIdx.x;
    __shared__ float red[8];

    float m = -3.4e38f;
    #pragma unroll
    for (int i = tid; i < U_TOK; i += 256) m = fmaxf(m, p[i]);
    m = warpMax(m);
    if ((tid & 31) == 0) red[tid >> 5] = m;
    __syncthreads();
    if (tid < 32) {
        float t = (tid < 8) ? red[tid] : -3.4e38f;
        t = warpMax(t);
        if (tid == 0) red[0] = t;
    }
    __syncthreads();
    const float rowmax = red[0];
    __syncthreads();

    float s = 0.f;
    #pragma unroll
    for (int i = tid; i < U_TOK; i += 256) {
        float e = __expf(p[i] - rowmax);
        p[i] = e;
        s += e;
    }
    s = warpSum(s);
    if ((tid & 31) == 0) red[tid >> 5] = s;
    __syncthreads();
    if (tid < 32) {
        float t = (tid < 8) ? red[tid] : 0.f;
        t = warpSum(t);
        if (tid == 0) red[0] = 1.f / t;
    }
    __syncthreads();
    const float inv = red[0];
    #pragma unroll
    for (int i = tid; i < U_TOK; i += 256) p[i] *= inv;
}

// ---------------- generic tiled SGEMM ----------------
// C[M,N] = A[M,K] * op(B) ; TB=1: B is [N,K] row-major (C = A B^T); TB=0: B is [K,N] row-major.
// Epilogues: 0 none; 1 v*scale + aux1[row,col]; 2 v + aux1[row,col];
//            3 gelu(v + aux2[col]); 4 aux1[row,col] + v + aux2[col]
template<int TB, int EPI>
__global__ __launch_bounds__(256, 2) void gemm_kernel(
    const float* __restrict__ A, const float* __restrict__ B, float* __restrict__ C,
    int K, int lda, int ldb, int ldc,
    size_t sA, size_t sB, size_t sC,
    const float* __restrict__ aux1, int ldaux,
    const float* __restrict__ aux2, float scale)
{
    A += (size_t)blockIdx.z * sA;
    B += (size_t)blockIdx.z * sB;
    C += (size_t)blockIdx.z * sC;

    __shared__ float As[8][128];
    __shared__ float Bs[8][128];

    const int tid = threadIdx.x;
    const int bm = blockIdx.y * 128;
    const int bn = blockIdx.x * 128;
    const int ty = tid >> 4;     // 0..15
    const int tx = tid & 15;     // 0..15

    float acc[8][8] = {};

    const int ar = tid >> 1;
    const int ak = (tid & 1) << 2;
    const float* Aptr = A + (size_t)(bm + ar) * lda + ak;

    const float* Bptr;
    int br = 0, bk = 0, bnn = 0;
    if (TB) { br = tid >> 1; bk = (tid & 1) << 2; Bptr = B + (size_t)(bn + br) * ldb + bk; }
    else    { bk = tid >> 5; bnn = (tid & 31) << 2; Bptr = B + (size_t)bk * ldb + bn + bnn; }

    for (int k0 = 0; k0 < K; k0 += 8) {
        float4 av = *reinterpret_cast<const float4*>(Aptr + k0);
        As[ak + 0][ar] = av.x; As[ak + 1][ar] = av.y;
        As[ak + 2][ar] = av.z; As[ak + 3][ar] = av.w;
        if (TB) {
            float4 bv = *reinterpret_cast<const float4*>(Bptr + k0);
            Bs[bk + 0][br] = bv.x; Bs[bk + 1][br] = bv.y;
            Bs[bk + 2][br] = bv.z; Bs[bk + 3][br] = bv.w;
        } else {
            float4 bv = *reinterpret_cast<const float4*>(Bptr + (size_t)k0 * ldb);
            *reinterpret_cast<float4*>(&Bs[bk][bnn]) = bv;
        }
        __syncthreads();

        #pragma unroll
        for (int kk = 0; kk < 8; kk++) {
            float af[8], bf[8];
            float4 a0 = *reinterpret_cast<const float4*>(&As[kk][ty * 8]);
            float4 a1 = *reinterpret_cast<const float4*>(&As[kk][ty * 8 + 4]);
            float4 b0 = *reinterpret_cast<const float4*>(&Bs[kk][tx * 8]);
            float4 b1 = *reinterpret_cast<const float4*>(&Bs[kk][tx * 8 + 4]);
            af[0]=a0.x; af[1]=a0.y; af[2]=a0.z; af[3]=a0.w;
            af[4]=a1.x; af[5]=a1.y; af[6]=a1.z; af[7]=a1.w;
            bf[0]=b0.x; bf[1]=b0.y; bf[2]=b0.z; bf[3]=b0.w;
            bf[4]=b1.x; bf[5]=b1.y; bf[6]=b1.z; bf[7]=b1.w;
            #pragma unroll
            for (int i = 0; i < 8; i++)
                #pragma unroll
                for (int j = 0; j < 8; j++)
                    acc[i][j] = fmaf(af[i], bf[j], acc[i][j]);
        }
        __syncthreads();
    }

    #pragma unroll
    for (int i = 0; i < 8; i++) {
        const int row = bm + ty * 8 + i;
        #pragma unroll
        for (int j = 0; j < 8; j++) {
            const int col = bn + tx * 8 + j;
            float v = acc[i][j];
            if (EPI == 1)      v = fmaf(v, scale, aux1[(size_t)row * ldaux + col]);
            else if (EPI == 2) v += aux1[(size_t)row * ldaux + col];
            else if (EPI == 3) { v += aux2[col]; v = 0.5f * v * (1.f + erff(v * 0.70710678118654752f)); }
            else if (EPI == 4) v = aux1[(size_t)row * ldaux + col] + v + aux2[col];
            C[(size_t)row * ldc + col] = v;
        }
    }
}

// ---------------- launch ----------------
extern "C" void kernel_launch(void* const* d_in, const int* in_sizes, int n_in,
                              void* d_out, int out_size)
{
    const float* x    = (const float*)d_in[0];
    const float* adj  = (const float*)d_in[1];
    const float* n1w  = (const float*)d_in[2];
    const float* n2w  = (const float*)d_in[3];
    const float* wq   = (const float*)d_in[4];
    const float* wk   = (const float*)d_in[5];
    const float* wv   = (const float*)d_in[6];
    const float* wo   = (const float*)d_in[7];
    const float* wup  = (const float*)d_in[8];
    const float* bup  = (const float*)d_in[9];
    const float* wdn  = (const float*)d_in[10];
    const float* bdn  = (const float*)d_in[11];
    float* out = (float*)d_out;

    float *h, *q, *k, *v, *sc, *ao, *x1, *h2, *ff;
    cudaGetSymbolAddress((void**)&h,  g_h);
    cudaGetSymbolAddress((void**)&q,  g_q);
    cudaGetSymbolAddress((void**)&k,  g_k);
    cudaGetSymbolAddress((void**)&v,  g_v);
    cudaGetSymbolAddress((void**)&sc, g_sc);
    cudaGetSymbolAddress((void**)&ao, g_ao);
    cudaGetSymbolAddress((void**)&x1, g_x1);
    cudaGetSymbolAddress((void**)&h2, g_h2);
    cudaGetSymbolAddress((void**)&ff, g_ff);

    const float scale = 1.f / sqrtf((float)DH);

    // 1. h = rmsnorm(x, n1w)
    rmsnorm_kernel<<<U_TOK, 256>>>(x, n1w, h);

    // 2. Q/K/V projections: [2048,2048] = h @ W^T
    dim3 gDD(D_MODEL / 128, U_TOK / 128, 1);
    gemm_kernel<1, 0><<<gDD, 256>>>(h, wq, q, D_MODEL, D_MODEL, D_MODEL, D_MODEL,
                                    0, 0, 0, nullptr, 0, nullptr, 0.f);
    gemm_kernel<1, 0><<<gDD, 256>>>(h, wk, k, D_MODEL, D_MODEL, D_MODEL, D_MODEL,
                                    0, 0, 0, nullptr, 0, nullptr, 0.f);
    gemm_kernel<1, 0><<<gDD, 256>>>(h, wv, v, D_MODEL, D_MODEL, D_MODEL, D_MODEL,
                                    0, 0, 0, nullptr, 0, nullptr, 0.f);

    // 3. scores[h] = Q_h K_h^T * scale + adj_bias   (batched over heads via z)
    dim3 gS(U_TOK / 128, U_TOK / 128, NH);
    gemm_kernel<1, 1><<<gS, 256>>>(q, k, sc, DH, D_MODEL, D_MODEL, U_TOK,
                                   (size_t)DH, (size_t)DH, (size_t)U_TOK * U_TOK,
                                   adj, U_TOK, nullptr, scale);

    // 4. softmax rows
    softmax_kernel<<<NH * U_TOK, 256>>>(sc);

    // 5. out_h = P_h V_h  (NN GEMM, N=128 per head)
    dim3 gP(DH / 128, U_TOK / 128, NH);
    gemm_kernel<0, 0><<<gP, 256>>>(sc, v, ao, U_TOK, U_TOK, D_MODEL, D_MODEL,
                                   (size_t)U_TOK * U_TOK, (size_t)DH, (size_t)DH,
                                   nullptr, 0, nullptr, 0.f);

    // 6. x1 = x + ao @ wo^T
    gemm_kernel<1, 2><<<gDD, 256>>>(ao, wo, x1, D_MODEL, D_MODEL, D_MODEL, D_MODEL,
                                    0, 0, 0, x, D_MODEL, nullptr, 0.f);

    // 7. h2 = rmsnorm(x1, n2w)
    rmsnorm_kernel<<<U_TOK, 256>>>(x1, n2w, h2);

    // 8. ff = gelu(h2 @ wup^T + bup)   [2048, 8192]
    dim3 gU(DFF / 128, U_TOK / 128, 1);
    gemm_kernel<1, 3><<<gU, 256>>>(h2, wup, ff, D_MODEL, D_MODEL, D_MODEL, DFF,
                                   0, 0, 0, nullptr, 0, bup, 0.f);

    // 9. out = x1 + ff @ wdn^T + bdn
    gemm_kernel<1, 4><<<gDD, 256>>>(ff, wdn, out, DFF, DFF, DFF, D_MODEL,
                                    0, 0, 0, x1, D_MODEL, bdn, 0.f);
}

// round 5
// speedup vs baseline: 3.1097x; 3.1097x over previous
#include <cuda_runtime.h>
#include <math.h>
#include <stdint.h>

#define U_TOK 2048
#define D_MODEL 2048
#define NH 16
#define DH 128
#define DFF 8192
#define EPSF 1e-6f

// ---------------- scratch (static device globals; no allocations) ----------------
__device__ float g_h   [U_TOK * D_MODEL];
__device__ float g_q   [U_TOK * D_MODEL];
__device__ float g_k   [U_TOK * D_MODEL];
__device__ float g_v   [U_TOK * D_MODEL];      // stored TRANSPOSED: Vt[D][U]
__device__ float g_sc  [(size_t)NH * U_TOK * U_TOK];   // 256 MB attention scores
__device__ float g_rinv[NH * U_TOK];           // per-row 1/sum for softmax
__device__ float g_ao  [U_TOK * D_MODEL];
__device__ float g_x1  [U_TOK * D_MODEL];
__device__ float g_h2  [U_TOK * D_MODEL];
__device__ float g_ff  [U_TOK * DFF];

// ---------------- reductions ----------------
__device__ __forceinline__ float warpSum(float v) {
    #pragma unroll
    for (int o = 16; o > 0; o >>= 1) v += __shfl_xor_sync(0xffffffffu, v, o);
    return v;
}
__device__ __forceinline__ float warpMax(float v) {
    #pragma unroll
    for (int o = 16; o > 0; o >>= 1) v = fmaxf(v, __shfl_xor_sync(0xffffffffu, v, o));
    return v;
}

// ---------------- rmsnorm: one block per row ----------------
__global__ __launch_bounds__(256) void rmsnorm_kernel(
    const float* __restrict__ x, const float* __restrict__ w, float* __restrict__ out)
{
    const int row = blockIdx.x;
    const float* xr = x + (size_t)row * D_MODEL;
    float* orow = out + (size_t)row * D_MODEL;
    const int tid = threadIdx.x;

    float ss = 0.f;
    #pragma unroll
    for (int i = tid; i < D_MODEL; i += 256) { float v = xr[i]; ss = fmaf(v, v, ss); }

    __shared__ float red[8];
    float s = warpSum(ss);
    if ((tid & 31) == 0) red[tid >> 5] = s;
    __syncthreads();
    if (tid < 32) {
        float t = (tid < 8) ? red[tid] : 0.f;
        t = warpSum(t);
        if (tid == 0) red[0] = rsqrtf(t * (1.f / D_MODEL) + EPSF);
    }
    __syncthreads();
    const float inv = red[0];
    #pragma unroll
    for (int i = tid; i < D_MODEL; i += 256) orow[i] = xr[i] * inv * w[i];
}

// ---------------- softmax (exp only; stores 1/rowsum, normalization fused into PV) ----------------
__global__ __launch_bounds__(256) void softmax_kernel(float* __restrict__ S, float* __restrict__ rinv)
{
    float* p = S + (size_t)blockIdx.x * U_TOK;
    const int tid = threadIdx.x;
    __shared__ float red[8];

    float m = -3.4e38f;
    #pragma unroll
    for (int i = tid; i < U_TOK; i += 256) m = fmaxf(m, p[i]);
    m = warpMax(m);
    if ((tid & 31) == 0) red[tid >> 5] = m;
    __syncthreads();
    if (tid < 32) {
        float t = (tid < 8) ? red[tid] : -3.4e38f;
        t = warpMax(t);
        if (tid == 0) red[0] = t;
    }
    __syncthreads();
    const float rowmax = red[0];
    __syncthreads();

    float s = 0.f;
    #pragma unroll
    for (int i = tid; i < U_TOK; i += 256) {
        float e = __expf(p[i] - rowmax);
        p[i] = e;
        s += e;
    }
    s = warpSum(s);
    if ((tid & 31) == 0) red[tid >> 5] = s;
    __syncthreads();
    if (tid < 32) {
        float t = (tid < 8) ? red[tid] : 0.f;
        t = warpSum(t);
        if (tid == 0) rinv[blockIdx.x] = 1.f / t;
    }
}

// ---------------- helpers ----------------
__device__ __forceinline__ void cpasync16(void* s, const void* g) {
    uint32_t sa = (uint32_t)__cvta_generic_to_shared(s);
    asm volatile("cp.async.ca.shared.global [%0], [%1], 16;\n" :: "r"(sa), "l"(g));
}
__device__ __forceinline__ uint32_t f2tf32(float f) {
    uint32_t r;
    asm volatile("cvt.rna.tf32.f32 %0, %1;" : "=r"(r) : "f"(f));
    return r;
}
__device__ __forceinline__ void mma_tf32(float* d, const uint32_t* a, const uint32_t* b) {
    asm volatile(
        "mma.sync.aligned.m16n8k8.row.col.f32.tf32.tf32.f32 "
        "{%0,%1,%2,%3}, {%4,%5,%6,%7}, {%8,%9}, {%0,%1,%2,%3};\n"
        : "+f"(d[0]), "+f"(d[1]), "+f"(d[2]), "+f"(d[3])
        : "r"(a[0]), "r"(a[1]), "r"(a[2]), "r"(a[3]), "r"(b[0]), "r"(b[1]));
}

// ---------------- TF32 tensor-core GEMM: C[M,N] = A[M,K] * B[N,K]^T ----------------
// Block tile 128x128, k-tile 16, 8 warps (4x2), warp tile 32x64, cp.async double buffer.
// Epilogues: 0 none; 1 v*scale + aux1[row,col]; 2 v + aux1[row,col];
//            3 gelu(v + aux2[col]); 4 aux1[row,col] + v + aux2[col];
//            5 v * aux1[z*U_TOK + row]    (softmax row normalization)
// TRANS=1: store transposed, C[col*ldc + row]
#define BK 16
#define LDP 20   // padded k-stride in smem (conflict-free for fragment pattern)

template<int EPI, int TRANS>
__global__ __launch_bounds__(256, 2) void mma_gemm(
    const float* __restrict__ A, const float* __restrict__ B, float* __restrict__ C,
    int K, int lda, int ldb, int ldc,
    size_t sA, size_t sB, size_t sC,
    const float* __restrict__ aux1, int ldaux,
    const float* __restrict__ aux2, float scale)
{
    A += (size_t)blockIdx.z * sA;
    B += (size_t)blockIdx.z * sB;
    C += (size_t)blockIdx.z * sC;

    __shared__ float As[2][128 * LDP];
    __shared__ float Bs[2][128 * LDP];

    const int tid  = threadIdx.x;
    const int lane = tid & 31;
    const int warp = tid >> 5;
    const int wm = (warp & 3) * 32;   // warp row offset in block tile
    const int wn = (warp >> 2) * 64;  // warp col offset
    const int bm = blockIdx.y * 128;
    const int bn = blockIdx.x * 128;
    const int tr = lane >> 2;         // 0..7
    const int tc = lane & 3;          // 0..3

    // global load coords (float4 each; 4 cp.async per thread per k-tile)
    const int lr = tid >> 2;          // 0..63
    const int lc = (tid & 3) * 4;     // 0,4,8,12

    float acc[2][8][4] = {};

    const float* Ag = A + (size_t)(bm + lr) * lda + lc;
    const float* Bg = B + (size_t)(bn + lr) * ldb + lc;
    const size_t lda64 = (size_t)64 * lda;
    const size_t ldb64 = (size_t)64 * ldb;

    const int niter = K / BK;

    // prefetch tile 0
    {
        float* a0 = &As[0][lr * LDP + lc];
        float* b0 = &Bs[0][lr * LDP + lc];
        cpasync16(a0, Ag);
        cpasync16(a0 + 64 * LDP, Ag + lda64);
        cpasync16(b0, Bg);
        cpasync16(b0 + 64 * LDP, Bg + ldb64);
        asm volatile("cp.async.commit_group;\n");
    }

    int buf = 0;
    for (int it = 0; it < niter; ++it) {
        if (it + 1 < niter) {
            const int k0 = (it + 1) * BK;
            float* a0 = &As[buf ^ 1][lr * LDP + lc];
            float* b0 = &Bs[buf ^ 1][lr * LDP + lc];
            cpasync16(a0, Ag + k0);
            cpasync16(a0 + 64 * LDP, Ag + lda64 + k0);
            cpasync16(b0, Bg + k0);
            cpasync16(b0 + 64 * LDP, Bg + ldb64 + k0);
            asm volatile("cp.async.commit_group;\n");
            asm volatile("cp.async.wait_group 1;\n");
        } else {
            asm volatile("cp.async.wait_group 0;\n");
        }
        __syncthreads();

        const float* Asb = As[buf];
        const float* Bsb = Bs[buf];

        #pragma unroll
        for (int ks = 0; ks < 2; ++ks) {
            const int k8 = ks * 8;
            uint32_t afr[2][4];
            #pragma unroll
            for (int mi = 0; mi < 2; ++mi) {
                const int base = (wm + mi * 16 + tr) * LDP + k8 + tc;
                afr[mi][0] = f2tf32(Asb[base]);
                afr[mi][1] = f2tf32(Asb[base + 8 * LDP]);
                afr[mi][2] = f2tf32(Asb[base + 4]);
                afr[mi][3] = f2tf32(Asb[base + 8 * LDP + 4]);
            }
            uint32_t bfr[8][2];
            #pragma unroll
            for (int ni = 0; ni < 8; ++ni) {
                const int base = (wn + ni * 8 + tr) * LDP + k8 + tc;
                bfr[ni][0] = f2tf32(Bsb[base]);
                bfr[ni][1] = f2tf32(Bsb[base + 4]);
            }
            #pragma unroll
            for (int mi = 0; mi < 2; ++mi)
                #pragma unroll
                for (int ni = 0; ni < 8; ++ni)
                    mma_tf32(acc[mi][ni], afr[mi], bfr[ni]);
        }
        __syncthreads();
        buf ^= 1;
    }

    // ---------------- epilogue ----------------
    #pragma unroll
    for (int mi = 0; mi < 2; ++mi) {
        #pragma unroll
        for (int ni = 0; ni < 8; ++ni) {
            const int row0 = bm + wm + mi * 16 + tr;
            const int col0 = bn + wn + ni * 8 + tc * 2;
            #pragma unroll
            for (int half = 0; half < 2; ++half) {
                const int row = row0 + half * 8;
                float e0 = acc[mi][ni][half * 2 + 0];
                float e1 = acc[mi][ni][half * 2 + 1];
                if (EPI == 1) {
                    e0 = fmaf(e0, scale, aux1[(size_t)row * ldaux + col0]);
                    e1 = fmaf(e1, scale, aux1[(size_t)row * ldaux + col0 + 1]);
                } else if (EPI == 2) {
                    e0 += aux1[(size_t)row * ldaux + col0];
                    e1 += aux1[(size_t)row * ldaux + col0 + 1];
                } else if (EPI == 3) {
                    e0 += aux2[col0];     e1 += aux2[col0 + 1];
                    e0 = 0.5f * e0 * (1.f + erff(e0 * 0.70710678118654752f));
                    e1 = 0.5f * e1 * (1.f + erff(e1 * 0.70710678118654752f));
                } else if (EPI == 4) {
                    e0 = aux1[(size_t)row * ldaux + col0]     + e0 + aux2[col0];
                    e1 = aux1[(size_t)row * ldaux + col0 + 1] + e1 + aux2[col0 + 1];
                } else if (EPI == 5) {
                    const float rs = aux1[(size_t)blockIdx.z * U_TOK + row];
                    e0 *= rs; e1 *= rs;
                }
                if (TRANS) {
                    C[(size_t)col0 * ldc + row]       = e0;
                    C[(size_t)(col0 + 1) * ldc + row] = e1;
                } else {
                    float2 v2 = make_float2(e0, e1);
                    *reinterpret_cast<float2*>(&C[(size_t)row * ldc + col0]) = v2;
                }
            }
        }
    }
}

// ---------------- launch ----------------
extern "C" void kernel_launch(void* const* d_in, const int* in_sizes, int n_in,
                              void* d_out, int out_size)
{
    const float* x    = (const float*)d_in[0];
    const float* adj  = (const float*)d_in[1];
    const float* n1w  = (const float*)d_in[2];
    const float* n2w  = (const float*)d_in[3];
    const float* wq   = (const float*)d_in[4];
    const float* wk   = (const float*)d_in[5];
    const float* wv   = (const float*)d_in[6];
    const float* wo   = (const float*)d_in[7];
    const float* wup  = (const float*)d_in[8];
    const float* bup  = (const float*)d_in[9];
    const float* wdn  = (const float*)d_in[10];
    const float* bdn  = (const float*)d_in[11];
    float* out = (float*)d_out;

    float *h, *q, *k, *v, *sc, *rinv, *ao, *x1, *h2, *ff;
    cudaGetSymbolAddress((void**)&h,    g_h);
    cudaGetSymbolAddress((void**)&q,    g_q);
    cudaGetSymbolAddress((void**)&k,    g_k);
    cudaGetSymbolAddress((void**)&v,    g_v);
    cudaGetSymbolAddress((void**)&sc,   g_sc);
    cudaGetSymbolAddress((void**)&rinv, g_rinv);
    cudaGetSymbolAddress((void**)&ao,   g_ao);
    cudaGetSymbolAddress((void**)&x1,   g_x1);
    cudaGetSymbolAddress((void**)&h2,   g_h2);
    cudaGetSymbolAddress((void**)&ff,   g_ff);

    const float scale = 1.f / sqrtf((float)DH);

    // 1. h = rmsnorm(x, n1w)
    rmsnorm_kernel<<<U_TOK, 256>>>(x, n1w, h);

    // 2. Q/K/V projections. V written TRANSPOSED: Vt[D][U].
    dim3 gDD(D_MODEL / 128, U_TOK / 128, 1);
    mma_gemm<0, 0><<<gDD, 256>>>(h, wq, q, D_MODEL, D_MODEL, D_MODEL, D_MODEL,
                                 0, 0, 0, nullptr, 0, nullptr, 0.f);
    mma_gemm<0, 0><<<gDD, 256>>>(h, wk, k, D_MODEL, D_MODEL, D_MODEL, D_MODEL,
                                 0, 0, 0, nullptr, 0, nullptr, 0.f);
    mma_gemm<0, 1><<<gDD, 256>>>(h, wv, v, D_MODEL, D_MODEL, D_MODEL, U_TOK,
                                 0, 0, 0, nullptr, 0, nullptr, 0.f);

    // 3. scores[h] = Q_h K_h^T * scale + adj_bias
    dim3 gS(U_TOK / 128, U_TOK / 128, NH);
    mma_gemm<1, 0><<<gS, 256>>>(q, k, sc, DH, D_MODEL, D_MODEL, U_TOK,
                                (size_t)DH, (size_t)DH, (size_t)U_TOK * U_TOK,
                                adj, U_TOK, nullptr, scale);

    // 4. softmax (exp + 1/rowsum; normalization fused into step 5)
    softmax_kernel<<<NH * U_TOK, 256>>>(sc, rinv);

    // 5. out_h = P_h Vt_h^T (A·B^T form thanks to transposed V), row-normalized in epilogue
    dim3 gP(DH / 128, U_TOK / 128, NH);
    mma_gemm<5, 0><<<gP, 256>>>(sc, v, ao, U_TOK, U_TOK, U_TOK, D_MODEL,
                                (size_t)U_TOK * U_TOK, (size_t)DH * U_TOK, (size_t)DH,
                                rinv, 0, nullptr, 0.f);

    // 6. x1 = x + ao @ wo^T
    mma_gemm<2, 0><<<gDD, 256>>>(ao, wo, x1, D_MODEL, D_MODEL, D_MODEL, D_MODEL,
                                 0, 0, 0, x, D_MODEL, nullptr, 0.f);

    // 7. h2 = rmsnorm(x1, n2w)
    rmsnorm_kernel<<<U_TOK, 256>>>(x1, n2w, h2);

    // 8. ff = gelu(h2 @ wup^T + bup)
    dim3 gU(DFF / 128, U_TOK / 128, 1);
    mma_gemm<3, 0><<<gU, 256>>>(h2, wup, ff, D_MODEL, D_MODEL, D_MODEL, DFF,
                                0, 0, 0, nullptr, 0, bup, 0.f);

    // 9. out = x1 + ff @ wdn^T + bdn
    mma_gemm<4, 0><<<gDD, 256>>>(ff, wdn, out, DFF, DFF, DFF, D_MODEL,
                                 0, 0, 0, x1, D_MODEL, bdn, 0.f);
}